// round 3
// baseline (speedup 1.0000x reference)
#include <cuda_runtime.h>
#include <cooperative_groups.h>

namespace cg = cooperative_groups;

#define BIN 256
#define IM 256
#define NPIX (IM * IM)          // 65536
#define NTHREADS_TOTAL (2 * NPIX)   // 131072 = 512 blocks x 256 threads

// Scratch: 4 histograms ({inp,ref} x {b0,b1}) of 256x256 float = 1 MB.
// Zero-initialized at module load; re-zeroed in phase B after reading, so
// every kernel_launch call (and every graph replay) starts from zeros.
__device__ float g_hist[4 * BIN * BIN];

// Triangular-kernel weight, numerics matching the reference exactly:
//   bias_k = 1 - 2k/256 (exact dyadic), a1 = u + bias_k, w = relu(1 - |a1|*255)
__device__ __forceinline__ float tri_w(float u, int k) {
    float a1 = u + (1.0f - (float)k * 0.0078125f);
    return fmaxf(0.0f, 1.0f - fabsf(a1) * 255.0f);
}

__global__ void fused_kernel(const float* __restrict__ inp,
                             const float* __restrict__ ref,
                             float* __restrict__ out) {
    cg::grid_group grid = cg::this_grid();
    int idx = blockIdx.x * blockDim.x + threadIdx.x;   // 0 .. 131071

    // ---------------- Phase A: scatter ----------------
    // hist2d[b,j,r] = sum_hw hb_j(ch1) * ha_r(ch0)
    {
        int b = idx >> 16;          // batch
        int p = idx & (NPIX - 1);   // pixel

#pragma unroll
        for (int t = 0; t < 2; ++t) {
            const float* img = (t == 0) ? inp : ref;
            float xa = img[(b * 2 + 0) * NPIX + p];   // ch0 -> r axis
            float xb = img[(b * 2 + 1) * NPIX + p];   // ch1 -> j axis
            float ua = (xa + 1.0f) * 0.5f;
            float ub = (xb + 1.0f) * 0.5f;

            // triangular support covers bins {floor(.), floor(.)+1};
            // usually only ONE has nonzero weight (support 1/255 vs half-pitch 1/256)
            int ka = (int)floorf(ua * 128.0f + 128.0f);
            int kb = (int)floorf(ub * 128.0f + 128.0f);

            float wa0 = tri_w(ua, ka);
            float wa1 = tri_w(ua, ka + 1);
            float wb0 = tri_w(ub, kb);
            float wb1 = tri_w(ub, kb + 1);

            bool a0 = wa0 > 0.0f;
            bool a1 = wa1 > 0.0f && (ka + 1) < BIN;
            bool b0 = wb0 > 0.0f;
            bool b1 = wb1 > 0.0f && (kb + 1) < BIN;

            float* H = g_hist + (t * 2 + b) * BIN * BIN;
            float* row0 = H + kb * BIN;
            if (b0) {
                if (a0) atomicAdd(row0 + ka,     wb0 * wa0);
                if (a1) atomicAdd(row0 + ka + 1, wb0 * wa1);
            }
            if (b1) {
                float* row1 = row0 + BIN;
                if (a0) atomicAdd(row1 + ka,     wb1 * wa0);
                if (a1) atomicAdd(row1 + ka + 1, wb1 * wa1);
            }
        }
    }

    grid.sync();

    // ---------------- Phase B: Huber loss + re-zero ----------------
    // out[b,0,j,r]: 2*65536 elements == one per thread, coalesced.
    {
        int b  = idx >> 16;
        int jr = idx & (BIN * BIN - 1);

        int oi = (0 * 2 + b) * BIN * BIN + jr;   // inp hist cell
        int gi = (1 * 2 + b) * BIN * BIN + jr;   // ref hist cell
        float hi = g_hist[oi];
        float hg = g_hist[gi];
        g_hist[oi] = 0.0f;
        g_hist[gi] = 0.0f;

        const float inv = 1.0f / (float)NPIX;
        float m = fabsf(hi - hg) * inv;
        out[idx] = (m < 0.01f) ? 50.0f * m * m : m - 0.005f;
    }
}

// ---------------------------------------------------------------------------
extern "C" void kernel_launch(void* const* d_in, const int* in_sizes, int n_in,
                              void* d_out, int out_size) {
    const float* inp = (const float*)d_in[0];
    const float* ref = (const float*)d_in[1];
    float* out = (float*)d_out;

    void* args[] = {(void*)&inp, (void*)&ref, (void*)&out};
    cudaLaunchCooperativeKernel((void*)fused_kernel,
                                dim3(NTHREADS_TOTAL / 256), dim3(256),
                                args, 0, (cudaStream_t)0);
}

// round 5
// speedup vs baseline: 2.0525x; 2.0525x over previous
#include <cuda_runtime.h>

#define BIN 256
#define IM 256
#define NPIX (IM * IM)          // 65536

// Scratch: 4 histograms ({inp,ref} x {b0,b1}) of 256x256 float = 1 MB.
// Zero-initialized at module load; re-zeroed by loss_kernel after each read,
// so every kernel_launch call (and every graph replay) starts from zeros.
__device__ float g_hist[4 * BIN * BIN];

// Triangular-kernel weight, numerics matching the reference exactly:
//   bias_k = 1 - 2k/256 (exact dyadic), a1 = u + bias_k, w = relu(1 - |a1|*255)
__device__ __forceinline__ float tri_w(float u, int k) {
    float a1 = u + (1.0f - (float)k * 0.0078125f);
    return fmaxf(0.0f, 1.0f - fabsf(a1) * 255.0f);
}

// ---------------------------------------------------------------------------
// Kernel 1: scatter. One thread per (image t, batch b, pixel p).
// hist2d[t,b,j,r] += hb_j(ch1) * ha_r(ch0); at most 2 bins active per axis,
// and usually exactly 1 (support 1/255 vs half-pitch 1/256) -> ~1.3 atomics
// per thread on average thanks to the zero-weight predicates.
// ---------------------------------------------------------------------------
__global__ void scatter_kernel(const float* __restrict__ inp,
                               const float* __restrict__ ref) {
    int idx = blockIdx.x * blockDim.x + threadIdx.x;   // 0 .. 4*NPIX-1
    int t = idx >> 17;            // image: 0=inp, 1=ref
    int b = (idx >> 16) & 1;      // batch
    int p = idx & (NPIX - 1);     // pixel

    const float* img = (t == 0) ? inp : ref;
    float xa = img[(b * 2 + 0) * NPIX + p];   // ch0 -> r axis (contig)
    float xb = img[(b * 2 + 1) * NPIX + p];   // ch1 -> j axis (row)
    float ua = (xa + 1.0f) * 0.5f;
    float ub = (xb + 1.0f) * 0.5f;

    int ka = (int)floorf(ua * 128.0f + 128.0f);
    int kb = (int)floorf(ub * 128.0f + 128.0f);

    float wa0 = tri_w(ua, ka);
    float wa1 = tri_w(ua, ka + 1);
    float wb0 = tri_w(ub, kb);
    float wb1 = tri_w(ub, kb + 1);

    bool a0 = wa0 > 0.0f;
    bool a1 = wa1 > 0.0f && (ka + 1) < BIN;
    bool b0 = wb0 > 0.0f;
    bool b1 = wb1 > 0.0f && (kb + 1) < BIN;

    float* H = g_hist + (t * 2 + b) * BIN * BIN;
    float* row0 = H + kb * BIN;
    if (b0) {
        if (a0) atomicAdd(row0 + ka,     wb0 * wa0);
        if (a1) atomicAdd(row0 + ka + 1, wb0 * wa1);
    }
    if (b1) {
        float* row1 = row0 + BIN;
        if (a0) atomicAdd(row1 + ka,     wb1 * wa0);
        if (a1) atomicAdd(row1 + ka + 1, wb1 * wa1);
    }
}

// ---------------------------------------------------------------------------
// Kernel 2: Huber loss between the two (mean-normalized) histograms and
// re-zero the cells for the next call. One thread per output element
// (131072 threads / 512 blocks -> latency well covered).
// ---------------------------------------------------------------------------
__global__ void loss_kernel(float* __restrict__ out) {
    int idx = blockIdx.x * blockDim.x + threadIdx.x;   // 0 .. 2*BIN*BIN-1
    int b  = idx >> 16;
    int jr = idx & (BIN * BIN - 1);

    int oi = (0 * 2 + b) * BIN * BIN + jr;   // inp hist cell
    int gi = (1 * 2 + b) * BIN * BIN + jr;   // ref hist cell
    float hi = g_hist[oi];
    float hg = g_hist[gi];
    g_hist[oi] = 0.0f;
    g_hist[gi] = 0.0f;

    const float inv = 1.0f / (float)NPIX;
    float m = fabsf(hi - hg) * inv;
    out[idx] = (m < 0.01f) ? 50.0f * m * m : m - 0.005f;
}

// ---------------------------------------------------------------------------
extern "C" void kernel_launch(void* const* d_in, const int* in_sizes, int n_in,
                              void* d_out, int out_size) {
    const float* inp = (const float*)d_in[0];
    const float* ref = (const float*)d_in[1];
    float* out = (float*)d_out;

    scatter_kernel<<<4 * NPIX / 256, 256>>>(inp, ref);
    loss_kernel<<<2 * BIN * BIN / 256, 256>>>(out);
}